// round 1
// baseline (speedup 1.0000x reference)
#include <cuda_runtime.h>
#include <cuda_bf16.h>
#include <math.h>

// ---------------------------------------------------------------------------
// DiT block: adaLN -> self-attn -> cross-attn -> gated MLP.  fp32 baseline.
// Shapes: B=8, N=1024, H=1152, NH=16, HD=72, CTX=768 (77 tok), MLP=4608.
// ---------------------------------------------------------------------------

#define Bsz   8
#define Ntok  1024
#define Hdim  1152
#define NHead 16
#define HeadD 72
#define CtxD  768
#define CtxT  77
#define MlpD  4608
#define Mrows (Bsz * Ntok)     // 8192
#define Crows (Bsz * CtxT)     // 616
#define ModW  (6 * Hdim)       // 6912

// ------------------------- scratch (no allocations) ------------------------
__device__ float g_mod  [Bsz * ModW];
__device__ float g_h    [Mrows * Hdim];
__device__ float g_qkv  [Mrows * 3 * Hdim];   // reused as cross-attn Q
__device__ float g_attno[Mrows * Hdim];
__device__ float g_x    [Mrows * Hdim];
__device__ float g_kbuf [Crows * Hdim];
__device__ float g_vbuf [Crows * Hdim];
__device__ float g_hid  [Mrows * MlpD];

// --------------------------- adaLN modulation ------------------------------
// mod[b, j] = silu(t_emb[b]) . ada_w[j] + ada_b[j];  grid 54 x 128 threads.
__global__ __launch_bounds__(128) void ada_kernel(
    const float* __restrict__ t_emb, const float* __restrict__ ada_w,
    const float* __restrict__ ada_b, float* __restrict__ mod) {
  __shared__ float se[Bsz * Hdim];
  int tid = threadIdx.x;
  for (int i = tid; i < Bsz * Hdim; i += 128) {
    float v = t_emb[i];
    se[i] = v / (1.f + __expf(-v));
  }
  __syncthreads();
  int j = blockIdx.x * 128 + tid;
  const float* w = ada_w + (size_t)j * Hdim;
  float acc[Bsz];
#pragma unroll
  for (int b = 0; b < Bsz; b++) acc[b] = 0.f;
  for (int k = 0; k < Hdim; k += 4) {
    float4 wv = *(const float4*)(w + k);
#pragma unroll
    for (int b = 0; b < Bsz; b++) {
      const float* s = se + b * Hdim + k;
      acc[b] += wv.x * s[0] + wv.y * s[1] + wv.z * s[2] + wv.w * s[3];
    }
  }
  float bb = ada_b[j];
#pragma unroll
  for (int b = 0; b < Bsz; b++) mod[b * ModW + j] = acc[b] + bb;
}

// ------------------------- LayerNorm + modulate -----------------------------
__global__ __launch_bounds__(256) void ln_mod_kernel(
    const float* __restrict__ x, const float* __restrict__ mod,
    int sh_off, int sc_off, float* __restrict__ out) {
  int row = blockIdx.x;
  int b = row >> 10;
  const float* xr = x + (size_t)row * Hdim;
  int tid = threadIdx.x;
  float s = 0.f, ss = 0.f;
  for (int i = tid; i < Hdim; i += 256) {
    float v = xr[i];
    s += v; ss += v * v;
  }
#pragma unroll
  for (int o = 16; o > 0; o >>= 1) {
    s  += __shfl_xor_sync(0xffffffffu, s, o);
    ss += __shfl_xor_sync(0xffffffffu, ss, o);
  }
  __shared__ float rs[8], rss[8], stat[2];
  int w = tid >> 5;
  if ((tid & 31) == 0) { rs[w] = s; rss[w] = ss; }
  __syncthreads();
  if (tid == 0) {
    float S = 0.f, SS = 0.f;
#pragma unroll
    for (int i = 0; i < 8; i++) { S += rs[i]; SS += rss[i]; }
    float mu = S * (1.f / Hdim);
    float var = SS * (1.f / Hdim) - mu * mu;
    stat[0] = mu;
    stat[1] = rsqrtf(var + 1e-6f);
  }
  __syncthreads();
  float mu = stat[0], rstd = stat[1];
  const float* sh = mod + b * ModW + sh_off * Hdim;
  const float* sc = mod + b * ModW + sc_off * Hdim;
  float* o = out + (size_t)row * Hdim;
  for (int i = tid; i < Hdim; i += 256)
    o[i] = (xr[i] - mu) * rstd * (1.f + sc[i]) + sh[i];
}

// ------------------------------ GEMM (NT) ----------------------------------
// C[M,N] = A[M,K] @ W[N,K]^T with fused epilogue.
__device__ __forceinline__ float gelu_tanh(float v) {
  const float c = 0.7978845608028654f;
  return 0.5f * v * (1.f + tanhf(c * (v + 0.044715f * v * v * v)));
}

#define EPI_BIAS    0
#define EPI_GELU    1
#define EPI_RESGATE 2

template <int EPI>
__global__ __launch_bounds__(256) void gemm_nt(
    const float* __restrict__ A, const float* __restrict__ W,
    const float* __restrict__ bias, const float* __restrict__ res,
    const float* __restrict__ gate, float* __restrict__ C,
    int M, int N, int K) {
  __shared__ float As[16][132];
  __shared__ float Bs[16][132];
  int tid = threadIdx.x;
  int tx = tid & 15, ty = tid >> 4;
  int m0 = blockIdx.y << 7, n0 = blockIdx.x << 7;

  float acc[8][8];
#pragma unroll
  for (int i = 0; i < 8; i++)
#pragma unroll
    for (int j = 0; j < 8; j++) acc[i][j] = 0.f;

  for (int k0 = 0; k0 < K; k0 += 16) {
#pragma unroll
    for (int i = 0; i < 2; i++) {
      int idx = tid + i * 256;
      int r = idx >> 2;
      int c4 = (idx & 3) << 2;
      int gm = m0 + r;
      float4 va = (gm < M) ? *(const float4*)(A + (size_t)gm * K + k0 + c4)
                           : make_float4(0.f, 0.f, 0.f, 0.f);
      As[c4 + 0][r] = va.x; As[c4 + 1][r] = va.y;
      As[c4 + 2][r] = va.z; As[c4 + 3][r] = va.w;
      int gn = n0 + r;  // N is always a multiple of 128 here
      float4 vb = *(const float4*)(W + (size_t)gn * K + k0 + c4);
      Bs[c4 + 0][r] = vb.x; Bs[c4 + 1][r] = vb.y;
      Bs[c4 + 2][r] = vb.z; Bs[c4 + 3][r] = vb.w;
    }
    __syncthreads();
#pragma unroll
    for (int kk = 0; kk < 16; kk++) {
      float a[8], b[8];
      *(float4*)(a)     = *(const float4*)&As[kk][ty * 8];
      *(float4*)(a + 4) = *(const float4*)&As[kk][ty * 8 + 4];
      *(float4*)(b)     = *(const float4*)&Bs[kk][tx * 8];
      *(float4*)(b + 4) = *(const float4*)&Bs[kk][tx * 8 + 4];
#pragma unroll
      for (int i = 0; i < 8; i++)
#pragma unroll
        for (int j = 0; j < 8; j++)
          acc[i][j] = fmaf(a[i], b[j], acc[i][j]);
    }
    __syncthreads();
  }

#pragma unroll
  for (int i = 0; i < 8; i++) {
    int m = m0 + ty * 8 + i;
    if (m >= M) break;
    int bq = m >> 10;
#pragma unroll
    for (int j = 0; j < 8; j++) {
      int n = n0 + tx * 8 + j;
      float v = acc[i][j];
      if (bias) v += bias[n];
      if (EPI == EPI_GELU) v = gelu_tanh(v);
      if (EPI == EPI_RESGATE) {
        float g = gate ? gate[bq * ModW + n] : 1.f;
        v = res[(size_t)m * N + n] + g * v;
      }
      C[(size_t)m * N + n] = v;
    }
  }
}

// ------------------------------ Attention ----------------------------------
// Flash-style, 64 q-rows x 64 kv-rows tiles, HD=72, online softmax.
#define AT_SMEM ((64 * 72 + 64 * 73 + 64 * 72 + 64 * 65 + 4 * 64) * 4)

__global__ __launch_bounds__(256) void attn_kernel(
    const float* __restrict__ Q, long long qbs, int ldq,
    const float* __restrict__ Kp, long long kbs, int ldk,
    const float* __restrict__ Vp, long long vbs, int ldv,
    float* __restrict__ O, long long obs, int ldo,
    int kv_len, float scale) {
  extern __shared__ float sm[];
  float* qs    = sm;                  // [64][72]
  float* ks    = qs + 64 * 72;        // [64][73]
  float* vs    = ks + 64 * 73;        // [64][72]
  float* ps    = vs + 64 * 72;        // [64][65]
  float* rowm  = ps + 64 * 65;
  float* rowa  = rowm + 64;
  float* rowls = rowa + 64;
  float* rowl  = rowls + 64;

  int b = blockIdx.z, h = blockIdx.y;
  int m0 = blockIdx.x * 64;
  const float* Qb = Q  + (size_t)b * qbs + h * HeadD;
  const float* Kb = Kp + (size_t)b * kbs + h * HeadD;
  const float* Vb = Vp + (size_t)b * vbs + h * HeadD;
  float*       Ob = O  + (size_t)b * obs + h * HeadD;

  int tid = threadIdx.x;
  int tx = tid & 15, ty = tid >> 4;
  int rr = tid & 63, cg = tid >> 6;

  for (int idx = tid; idx < 64 * 72; idx += 256) {
    int r = idx / 72, c = idx % 72;
    qs[r * 72 + c] = Qb[(size_t)(m0 + r) * ldq + c] * scale;
  }
  if (tid < 64) { rowm[tid] = -1e30f; rowl[tid] = 0.f; }
  float oacc[18];
#pragma unroll
  for (int c = 0; c < 18; c++) oacc[c] = 0.f;
  __syncthreads();

  for (int j0 = 0; j0 < kv_len; j0 += 64) {
    for (int idx = tid; idx < 64 * 72; idx += 256) {
      int r = idx / 72, c = idx % 72;
      int jj = j0 + r;
      bool ok = jj < kv_len;
      ks[r * 73 + c] = ok ? Kb[(size_t)jj * ldk + c] : 0.f;
      vs[r * 72 + c] = ok ? Vb[(size_t)jj * ldv + c] : 0.f;
    }
    __syncthreads();

    float s[4][4];
#pragma unroll
    for (int i = 0; i < 4; i++)
#pragma unroll
      for (int j = 0; j < 4; j++) s[i][j] = 0.f;

#pragma unroll 4
    for (int k = 0; k < HeadD; k++) {
      float qv[4], kv[4];
#pragma unroll
      for (int i = 0; i < 4; i++) qv[i] = qs[(ty * 4 + i) * 72 + k];
#pragma unroll
      for (int j = 0; j < 4; j++) kv[j] = ks[(tx * 4 + j) * 73 + k];
#pragma unroll
      for (int i = 0; i < 4; i++)
#pragma unroll
        for (int j = 0; j < 4; j++)
          s[i][j] = fmaf(qv[i], kv[j], s[i][j]);
    }
#pragma unroll
    for (int j = 0; j < 4; j++)
      if (j0 + tx * 4 + j >= kv_len)
#pragma unroll
        for (int i = 0; i < 4; i++) s[i][j] = -1e30f;

    float mx[4];
#pragma unroll
    for (int i = 0; i < 4; i++)
      mx[i] = fmaxf(fmaxf(s[i][0], s[i][1]), fmaxf(s[i][2], s[i][3]));
#pragma unroll
    for (int o = 8; o > 0; o >>= 1)
#pragma unroll
      for (int i = 0; i < 4; i++)
        mx[i] = fmaxf(mx[i], __shfl_xor_sync(0xffffffffu, mx[i], o));
    if (tx == 0) {
#pragma unroll
      for (int i = 0; i < 4; i++) {
        int r = ty * 4 + i;
        float mo = rowm[r];
        float mn = fmaxf(mo, mx[i]);
        rowm[r] = mn;
        rowa[r] = __expf(mo - mn);
      }
    }
    __syncthreads();

    float ls[4];
#pragma unroll
    for (int i = 0; i < 4; i++) {
      float mn = rowm[ty * 4 + i];
      ls[i] = 0.f;
#pragma unroll
      for (int j = 0; j < 4; j++) {
        float p = __expf(s[i][j] - mn);
        ps[(ty * 4 + i) * 65 + tx * 4 + j] = p;
        ls[i] += p;
      }
    }
#pragma unroll
    for (int o = 8; o > 0; o >>= 1)
#pragma unroll
      for (int i = 0; i < 4; i++)
        ls[i] += __shfl_xor_sync(0xffffffffu, ls[i], o);
    if (tx == 0)
#pragma unroll
      for (int i = 0; i < 4; i++) rowls[ty * 4 + i] = ls[i];
    __syncthreads();

    float al = rowa[rr];
#pragma unroll
    for (int c = 0; c < 18; c++) oacc[c] *= al;
#pragma unroll 2
    for (int kk = 0; kk < 64; kk++) {
      float p = ps[rr * 65 + kk];
      const float* vrow = vs + kk * 72 + cg * 18;
#pragma unroll
      for (int c = 0; c < 18; c++) oacc[c] = fmaf(p, vrow[c], oacc[c]);
    }
    if (cg == 0) rowl[rr] = rowl[rr] * al + rowls[rr];
    __syncthreads();
  }

  float inv = 1.f / rowl[rr];
  float* orow = Ob + (size_t)(m0 + rr) * ldo + cg * 18;
#pragma unroll
  for (int c = 0; c < 18; c++) orow[c] = oacc[c] * inv;
}

// ------------------------------ launcher -----------------------------------
extern "C" void kernel_launch(void* const* d_in, const int* in_sizes, int n_in,
                              void* d_out, int out_size) {
  (void)in_sizes; (void)n_in; (void)out_size;
  const float* x        = (const float*)d_in[0];
  const float* c        = (const float*)d_in[1];
  const float* t_emb    = (const float*)d_in[2];
  const float* qkv_w    = (const float*)d_in[3];
  const float* qkv_b    = (const float*)d_in[4];
  const float* proj_w   = (const float*)d_in[5];
  const float* proj_b   = (const float*)d_in[6];
  const float* to_q_w   = (const float*)d_in[7];
  const float* to_k_w   = (const float*)d_in[8];
  const float* to_v_w   = (const float*)d_in[9];
  const float* to_out_w = (const float*)d_in[10];
  const float* to_out_b = (const float*)d_in[11];
  const float* mlp_w1   = (const float*)d_in[12];
  const float* mlp_b1   = (const float*)d_in[13];
  const float* mlp_w2   = (const float*)d_in[14];
  const float* mlp_b2   = (const float*)d_in[15];
  const float* ada_w    = (const float*)d_in[16];
  const float* ada_b    = (const float*)d_in[17];
  float* out = (float*)d_out;

  float *mod, *hbuf, *qkv, *attno, *xb, *kb, *vb, *hid;
  cudaGetSymbolAddress((void**)&mod,   g_mod);
  cudaGetSymbolAddress((void**)&hbuf,  g_h);
  cudaGetSymbolAddress((void**)&qkv,   g_qkv);
  cudaGetSymbolAddress((void**)&attno, g_attno);
  cudaGetSymbolAddress((void**)&xb,    g_x);
  cudaGetSymbolAddress((void**)&kb,    g_kbuf);
  cudaGetSymbolAddress((void**)&vb,    g_vbuf);
  cudaGetSymbolAddress((void**)&hid,   g_hid);

  cudaFuncSetAttribute(attn_kernel,
                       cudaFuncAttributeMaxDynamicSharedMemorySize, AT_SMEM);

  float scale = 1.f / sqrtf((float)HeadD);

  // adaLN
  ada_kernel<<<ModW / 128, 128>>>(t_emb, ada_w, ada_b, mod);
  // LN + modulate (msa)
  ln_mod_kernel<<<Mrows, 256>>>(x, mod, 0, 1, hbuf);
  // qkv
  {
    dim3 g(3 * Hdim / 128, Mrows / 128);
    gemm_nt<EPI_BIAS><<<g, 256>>>(hbuf, qkv_w, qkv_b, nullptr, nullptr, qkv,
                                  Mrows, 3 * Hdim, Hdim);
  }
  // self-attention
  {
    dim3 g(Ntok / 64, NHead, Bsz);
    attn_kernel<<<g, 256, AT_SMEM>>>(
        qkv,              (long long)Ntok * 3 * Hdim, 3 * Hdim,
        qkv + Hdim,       (long long)Ntok * 3 * Hdim, 3 * Hdim,
        qkv + 2 * Hdim,   (long long)Ntok * 3 * Hdim, 3 * Hdim,
        attno,            (long long)Ntok * Hdim,     Hdim,
        Ntok, scale);
  }
  // proj + gated residual -> xb
  {
    dim3 g(Hdim / 128, Mrows / 128);
    gemm_nt<EPI_RESGATE><<<g, 256>>>(attno, proj_w, proj_b, x,
                                     mod + 2 * Hdim, xb, Mrows, Hdim, Hdim);
    // cross-attn q (reuse qkv buffer)
    gemm_nt<EPI_BIAS><<<g, 256>>>(xb, to_q_w, nullptr, nullptr, nullptr, qkv,
                                  Mrows, Hdim, Hdim);
  }
  // cross-attn k, v from context
  {
    dim3 g(Hdim / 128, (Crows + 127) / 128);
    gemm_nt<EPI_BIAS><<<g, 256>>>(c, to_k_w, nullptr, nullptr, nullptr, kb,
                                  Crows, Hdim, CtxD);
    gemm_nt<EPI_BIAS><<<g, 256>>>(c, to_v_w, nullptr, nullptr, nullptr, vb,
                                  Crows, Hdim, CtxD);
  }
  // cross-attention
  {
    dim3 g(Ntok / 64, NHead, Bsz);
    attn_kernel<<<g, 256, AT_SMEM>>>(
        qkv,   (long long)Ntok * Hdim, Hdim,
        kb,    (long long)CtxT * Hdim, Hdim,
        vb,    (long long)CtxT * Hdim, Hdim,
        attno, (long long)Ntok * Hdim, Hdim,
        CtxT, scale);
  }
  // to_out + residual (in place on xb)
  {
    dim3 g(Hdim / 128, Mrows / 128);
    gemm_nt<EPI_RESGATE><<<g, 256>>>(attno, to_out_w, to_out_b, xb, nullptr,
                                     xb, Mrows, Hdim, Hdim);
  }
  // LN + modulate (mlp)
  ln_mod_kernel<<<Mrows, 256>>>(xb, mod, 3, 4, hbuf);
  // MLP
  {
    dim3 g1(MlpD / 128, Mrows / 128);
    gemm_nt<EPI_GELU><<<g1, 256>>>(hbuf, mlp_w1, mlp_b1, nullptr, nullptr,
                                   hid, Mrows, MlpD, Hdim);
    dim3 g2(Hdim / 128, Mrows / 128);
    gemm_nt<EPI_RESGATE><<<g2, 256>>>(hid, mlp_w2, mlp_b2, xb,
                                      mod + 5 * Hdim, out, Mrows, Hdim, MlpD);
  }
}

// round 3
// speedup vs baseline: 1.8985x; 1.8985x over previous
#include <cuda_runtime.h>
#include <cuda_bf16.h>
#include <math.h>
#include <stdint.h>

// ---------------------------------------------------------------------------
// DiT block. Round 3: all GEMMs on bf16 tensor cores with hi/lo split
// (3-MMA compensation => ~fp32 accuracy), cp.async double buffering.
// ---------------------------------------------------------------------------

#define Bsz   8
#define Ntok  1024
#define Hdim  1152
#define NHead 16
#define HeadD 72
#define CtxD  768
#define CtxT  77
#define MlpD  4608
#define Mrows (Bsz * Ntok)     // 8192
#define Crows (Bsz * CtxT)     // 616
#define ModW  (6 * Hdim)       // 6912

typedef __nv_bfloat16 bf16;
typedef __nv_bfloat162 bf162;

// ------------------------- scratch (no allocations) ------------------------
__device__ float g_mod [Bsz * ModW];
__device__ float g_qkv [Mrows * 3 * Hdim];     // also cross-attn Q
__device__ float g_xb  [Mrows * Hdim];
__device__ float g_kb  [Crows * Hdim];
__device__ float g_vb  [Crows * Hdim];

// bf16 hi/lo planes
__device__ bf16 g_ln_h [Mrows * Hdim],  g_ln_l [Mrows * Hdim];
__device__ bf16 g_at_h [Mrows * Hdim],  g_at_l [Mrows * Hdim];
__device__ bf16 g_xb_h [Mrows * Hdim],  g_xb_l [Mrows * Hdim];
__device__ bf16 g_hid_h[Mrows * MlpD],  g_hid_l[Mrows * MlpD];
__device__ bf16 g_c_h  [Crows * CtxD],  g_c_l  [Crows * CtxD];
__device__ bf16 g_wqkv_h[3 * Hdim * Hdim], g_wqkv_l[3 * Hdim * Hdim];
__device__ bf16 g_wpr_h [Hdim * Hdim],     g_wpr_l [Hdim * Hdim];
__device__ bf16 g_wq_h  [Hdim * Hdim],     g_wq_l  [Hdim * Hdim];
__device__ bf16 g_wk_h  [Hdim * CtxD],     g_wk_l  [Hdim * CtxD];
__device__ bf16 g_wv_h  [Hdim * CtxD],     g_wv_l  [Hdim * CtxD];
__device__ bf16 g_wo_h  [Hdim * Hdim],     g_wo_l  [Hdim * Hdim];
__device__ bf16 g_w1_h  [MlpD * Hdim],     g_w1_l  [MlpD * Hdim];
__device__ bf16 g_w2_h  [Hdim * MlpD],     g_w2_l  [Hdim * MlpD];

// ------------------------------ helpers ------------------------------------
__device__ __forceinline__ void split_bf16(float v, bf16& h, bf16& l) {
  h = __float2bfloat16(v);
  l = __float2bfloat16(v - __bfloat162float(h));
}

// fp32 -> hi/lo planes
__global__ __launch_bounds__(256) void cvt_kernel(
    const float* __restrict__ in, bf16* __restrict__ hi,
    bf16* __restrict__ lo, int n) {
  int i = (blockIdx.x * 256 + threadIdx.x) * 4;
  if (i >= n) return;
  float4 v = *(const float4*)(in + i);
  bf16 h0, l0, h1, l1, h2, l2, h3, l3;
  split_bf16(v.x, h0, l0); split_bf16(v.y, h1, l1);
  split_bf16(v.z, h2, l2); split_bf16(v.w, h3, l3);
  *(bf162*)(hi + i)     = __halves2bfloat162(h0, h1);
  *(bf162*)(hi + i + 2) = __halves2bfloat162(h2, h3);
  *(bf162*)(lo + i)     = __halves2bfloat162(l0, l1);
  *(bf162*)(lo + i + 2) = __halves2bfloat162(l2, l3);
}

// --------------------------- adaLN modulation ------------------------------
__global__ __launch_bounds__(128) void ada_kernel(
    const float* __restrict__ t_emb, const float* __restrict__ ada_w,
    const float* __restrict__ ada_b, float* __restrict__ mod) {
  __shared__ float se[Bsz * Hdim];
  int tid = threadIdx.x;
  for (int i = tid; i < Bsz * Hdim; i += 128) {
    float v = t_emb[i];
    se[i] = v / (1.f + __expf(-v));
  }
  __syncthreads();
  int j = blockIdx.x * 128 + tid;
  const float* w = ada_w + (size_t)j * Hdim;
  float acc[Bsz];
#pragma unroll
  for (int b = 0; b < Bsz; b++) acc[b] = 0.f;
  for (int k = 0; k < Hdim; k += 4) {
    float4 wv = *(const float4*)(w + k);
#pragma unroll
    for (int b = 0; b < Bsz; b++) {
      const float* s = se + b * Hdim + k;
      acc[b] += wv.x * s[0] + wv.y * s[1] + wv.z * s[2] + wv.w * s[3];
    }
  }
  float bb = ada_b[j];
#pragma unroll
  for (int b = 0; b < Bsz; b++) mod[b * ModW + j] = acc[b] + bb;
}

// ----------------- LayerNorm + modulate -> bf16 hi/lo -----------------------
__global__ __launch_bounds__(256) void ln_mod_kernel(
    const float* __restrict__ x, const float* __restrict__ mod,
    int sh_off, int sc_off, bf16* __restrict__ ohi, bf16* __restrict__ olo) {
  int row = blockIdx.x;
  int b = row >> 10;
  const float* xr = x + (size_t)row * Hdim;
  int tid = threadIdx.x;
  float s = 0.f, ss = 0.f;
  for (int i = tid; i < Hdim; i += 256) {
    float v = xr[i];
    s += v; ss += v * v;
  }
#pragma unroll
  for (int o = 16; o > 0; o >>= 1) {
    s  += __shfl_xor_sync(0xffffffffu, s, o);
    ss += __shfl_xor_sync(0xffffffffu, ss, o);
  }
  __shared__ float rs[8], rss[8], stat[2];
  int w = tid >> 5;
  if ((tid & 31) == 0) { rs[w] = s; rss[w] = ss; }
  __syncthreads();
  if (tid == 0) {
    float S = 0.f, SS = 0.f;
#pragma unroll
    for (int i = 0; i < 8; i++) { S += rs[i]; SS += rss[i]; }
    float mu = S * (1.f / Hdim);
    float var = SS * (1.f / Hdim) - mu * mu;
    stat[0] = mu;
    stat[1] = rsqrtf(var + 1e-6f);
  }
  __syncthreads();
  float mu = stat[0], rstd = stat[1];
  const float* sh = mod + b * ModW + sh_off * Hdim;
  const float* sc = mod + b * ModW + sc_off * Hdim;
  bf16* oh = ohi + (size_t)row * Hdim;
  bf16* ol = olo + (size_t)row * Hdim;
  for (int i = tid; i < Hdim; i += 256) {
    float v = (xr[i] - mu) * rstd * (1.f + sc[i]) + sh[i];
    bf16 h, l; split_bf16(v, h, l);
    oh[i] = h; ol[i] = l;
  }
}

// ------------------- tensor-core GEMM (NT, bf16 x3) -------------------------
__device__ __forceinline__ float gelu_tanh(float v) {
  const float c = 0.7978845608028654f;
  return 0.5f * v * (1.f + tanhf(c * (v + 0.044715f * v * v * v)));
}

#define EPI_BIAS    0
#define EPI_GELU    1
#define EPI_RESGATE 2

__device__ __forceinline__ void mma_bf16(float c[4], const uint32_t a[4],
                                         const uint32_t b[2]) {
  asm volatile(
      "mma.sync.aligned.m16n8k16.row.col.f32.bf16.bf16.f32 "
      "{%0,%1,%2,%3}, {%4,%5,%6,%7}, {%8,%9}, {%0,%1,%2,%3};"
      : "+f"(c[0]), "+f"(c[1]), "+f"(c[2]), "+f"(c[3])
      : "r"(a[0]), "r"(a[1]), "r"(a[2]), "r"(a[3]), "r"(b[0]), "r"(b[1]));
}

__device__ __forceinline__ void ldsm4(uint32_t r[4], uint32_t addr) {
  asm volatile("ldmatrix.sync.aligned.m8n8.x4.shared.b16 {%0,%1,%2,%3}, [%4];"
               : "=r"(r[0]), "=r"(r[1]), "=r"(r[2]), "=r"(r[3]) : "r"(addr));
}

__device__ __forceinline__ void cp16(uint32_t dst, const void* src, bool p) {
  int sz = p ? 16 : 0;
  asm volatile("cp.async.cg.shared.global [%0], [%1], 16, %2;\n"
               :: "r"(dst), "l"(src), "r"(sz));
}

// smem: per stage 4 tiles (Ah, Al, Bh, Bl), each 128 rows x 32 bf16, stride
// 80 bytes (40 bf16) -> conflict-free ldmatrix. Stage = 40960 B, 2 stages.
#define TILE_B  10240
#define STAGE_B 40960
#define GSMEM   (2 * STAGE_B)

template <int EPI, bool OUTF, bool OUTB>
__global__ __launch_bounds__(256, 2) void gemm_tc(
    const bf16* __restrict__ Ah, const bf16* __restrict__ Al,
    const bf16* __restrict__ Wh, const bf16* __restrict__ Wl,
    const float* __restrict__ bias, const float* __restrict__ res,
    const float* __restrict__ gate, float* __restrict__ C,
    bf16* __restrict__ Chi, bf16* __restrict__ Clo,
    int M, int N, int K) {
  extern __shared__ char smc[];
  uint32_t sbase = (uint32_t)__cvta_generic_to_shared(smc);
  int tid = threadIdx.x;
  int warp = tid >> 5, lane = tid & 31;
  int wm = warp & 3, wn = warp >> 2;   // 4 warps M x 2 warps N
  int m0 = blockIdx.y << 7, n0 = blockIdx.x << 7;

  float acc[2][8][4];
#pragma unroll
  for (int mt = 0; mt < 2; mt++)
#pragma unroll
    for (int nt = 0; nt < 8; nt++)
#pragma unroll
      for (int f = 0; f < 4; f++) acc[mt][nt][f] = 0.f;

  // ldmatrix lane offsets (bytes within a stage)
  int lq = lane & 7, lb = (lane >> 3) & 1, lh = lane >> 4;
  uint32_t offA[2], offB[4];
#pragma unroll
  for (int mt = 0; mt < 2; mt++)
    offA[mt] = (uint32_t)((wm * 32 + mt * 16 + lq + lb * 8) * 80 + lh * 16);
#pragma unroll
  for (int j = 0; j < 4; j++)
    offB[j] = (uint32_t)(2 * TILE_B +
                         (wn * 64 + j * 16 + lq + lh * 8) * 80 + lb * 16);

  // cp.async chunk coords: chunk = tid (+256); row = chunk/4, 16B col
  int r0c = tid >> 2, c0b = (tid & 3) * 16;
  int r1c = (tid + 256) >> 2, c1b = ((tid + 256) & 3) * 16;

  const int nk = K >> 5;

  auto issue = [&](int k0, int s) {
    uint32_t st = sbase + s * STAGE_B;
#pragma unroll
    for (int i = 0; i < 2; i++) {
      int row = i ? r1c : r0c;
      int cb  = i ? c1b : c0b;
      int ce  = cb >> 1;                       // bf16 elems
      bool am = (m0 + row) < M;
      int ra = am ? (m0 + row) : 0;
      const bf16* sa_h = Ah + (size_t)ra * K + k0 + ce;
      const bf16* sa_l = Al + (size_t)ra * K + k0 + ce;
      const bf16* sb_h = Wh + (size_t)(n0 + row) * K + k0 + ce;
      const bf16* sb_l = Wl + (size_t)(n0 + row) * K + k0 + ce;
      uint32_t d = st + row * 80 + cb;
      cp16(d,              sa_h, am);
      cp16(d + TILE_B,     sa_l, am);
      cp16(d + 2 * TILE_B, sb_h, true);
      cp16(d + 3 * TILE_B, sb_l, true);
    }
    asm volatile("cp.async.commit_group;\n");
  };

  issue(0, 0);
  for (int kt = 0; kt < nk; kt++) {
    int s = kt & 1;
    if (kt + 1 < nk) {
      issue((kt + 1) << 5, s ^ 1);
      asm volatile("cp.async.wait_group 1;\n");
    } else {
      asm volatile("cp.async.wait_group 0;\n");
    }
    __syncthreads();

    uint32_t sb = sbase + s * STAGE_B;
#pragma unroll
    for (int ks = 0; ks < 2; ks++) {
      uint32_t ah[2][4], al[2][4];
#pragma unroll
      for (int mt = 0; mt < 2; mt++) {
        ldsm4(ah[mt], sb + offA[mt] + ks * 32);
        ldsm4(al[mt], sb + offA[mt] + TILE_B + ks * 32);
      }
#pragma unroll
      for (int j = 0; j < 4; j++) {
        uint32_t bh[4], bl[4];
        ldsm4(bh, sb + offB[j] + ks * 32);
        ldsm4(bl, sb + offB[j] + TILE_B + ks * 32);
#pragma unroll
        for (int mt = 0; mt < 2; mt++) {
          mma_bf16(acc[mt][2 * j],     ah[mt], bh);
          mma_bf16(acc[mt][2 * j],     ah[mt], bl);
          mma_bf16(acc[mt][2 * j],     al[mt], bh);
          mma_bf16(acc[mt][2 * j + 1], ah[mt], bh + 2);
          mma_bf16(acc[mt][2 * j + 1], ah[mt], bl + 2);
          mma_bf16(acc[mt][2 * j + 1], al[mt], bh + 2);
        }
      }
    }
    __syncthreads();
  }

  // ---- epilogue ----
  int g = lane >> 2, tg = lane & 3;
#pragma unroll
  for (int mt = 0; mt < 2; mt++) {
#pragma unroll
    for (int half = 0; half < 2; half++) {
      int m = m0 + wm * 32 + mt * 16 + g + half * 8;
      if (m >= M) continue;
      int bq = m >> 10;
#pragma unroll
      for (int nt = 0; nt < 8; nt++) {
        int n = n0 + wn * 64 + nt * 8 + tg * 2;
        float v0 = acc[mt][nt][half * 2 + 0];
        float v1 = acc[mt][nt][half * 2 + 1];
        if (bias) { v0 += bias[n]; v1 += bias[n + 1]; }
        if (EPI == EPI_GELU) { v0 = gelu_tanh(v0); v1 = gelu_tanh(v1); }
        if (EPI == EPI_RESGATE) {
          float g0 = 1.f, g1 = 1.f;
          if (gate) { g0 = gate[bq * ModW + n]; g1 = gate[bq * ModW + n + 1]; }
          v0 = res[(size_t)m * N + n] + g0 * v0;
          v1 = res[(size_t)m * N + n + 1] + g1 * v1;
        }
        if (OUTF)
          *(float2*)(C + (size_t)m * N + n) = make_float2(v0, v1);
        if (OUTB) {
          bf16 h0, l0, h1, l1;
          split_bf16(v0, h0, l0);
          split_bf16(v1, h1, l1);
          *(bf162*)(Chi + (size_t)m * N + n) = __halves2bfloat162(h0, h1);
          *(bf162*)(Clo + (size_t)m * N + n) = __halves2bfloat162(l0, l1);
        }
      }
    }
  }
}

// ------------------------------ Attention ----------------------------------
#define AT_SMEM ((64 * 72 + 64 * 73 + 64 * 72 + 64 * 65 + 4 * 64) * 4)

__global__ __launch_bounds__(256) void attn_kernel(
    const float* __restrict__ Q, long long qbs, int ldq,
    const float* __restrict__ Kp, long long kbs, int ldk,
    const float* __restrict__ Vp, long long vbs, int ldv,
    bf16* __restrict__ Ohi, bf16* __restrict__ Olo,
    int kv_len, float scale) {
  extern __shared__ float sm[];
  float* qs    = sm;
  float* ks    = qs + 64 * 72;
  float* vs    = ks + 64 * 73;
  float* ps    = vs + 64 * 72;
  float* rowm  = ps + 64 * 65;
  float* rowa  = rowm + 64;
  float* rowls = rowa + 64;
  float* rowl  = rowls + 64;

  int b = blockIdx.z, h = blockIdx.y;
  int m0 = blockIdx.x * 64;
  const float* Qb = Q  + (size_t)b * qbs + h * HeadD;
  const float* Kb = Kp + (size_t)b * kbs + h * HeadD;
  const float* Vb = Vp + (size_t)b * vbs + h * HeadD;
  size_t obase = ((size_t)b * Ntok) * Hdim + h * HeadD;

  int tid = threadIdx.x;
  int tx = tid & 15, ty = tid >> 4;
  int rr = tid & 63, cg = tid >> 6;

  for (int idx = tid; idx < 64 * 72; idx += 256) {
    int r = idx / 72, c = idx % 72;
    qs[r * 72 + c] = Qb[(size_t)(m0 + r) * ldq + c] * scale;
  }
  if (tid < 64) { rowm[tid] = -1e30f; rowl[tid] = 0.f; }
  float oacc[18];
#pragma unroll
  for (int c = 0; c < 18; c++) oacc[c] = 0.f;
  __syncthreads();

  for (int j0 = 0; j0 < kv_len; j0 += 64) {
    for (int idx = tid; idx < 64 * 72; idx += 256) {
      int r = idx / 72, c = idx % 72;
      int jj = j0 + r;
      bool ok = jj < kv_len;
      ks[r * 73 + c] = ok ? Kb[(size_t)jj * ldk + c] : 0.f;
      vs[r * 72 + c] = ok ? Vb[(size_t)jj * ldv + c] : 0.f;
    }
    __syncthreads();

    float s[4][4];
#pragma unroll
    for (int i = 0; i < 4; i++)
#pragma unroll
      for (int j = 0; j < 4; j++) s[i][j] = 0.f;

#pragma unroll 4
    for (int k = 0; k < HeadD; k++) {
      float qv[4], kv[4];
#pragma unroll
      for (int i = 0; i < 4; i++) qv[i] = qs[(ty * 4 + i) * 72 + k];
#pragma unroll
      for (int j = 0; j < 4; j++) kv[j] = ks[(tx * 4 + j) * 73 + k];
#pragma unroll
      for (int i = 0; i < 4; i++)
#pragma unroll
        for (int j = 0; j < 4; j++)
          s[i][j] = fmaf(qv[i], kv[j], s[i][j]);
    }
#pragma unroll
    for (int j = 0; j < 4; j++)
      if (j0 + tx * 4 + j >= kv_len)
#pragma unroll
        for (int i = 0; i < 4; i++) s[i][j] = -1e30f;

    float mx[4];
#pragma unroll
    for (int i = 0; i < 4; i++)
      mx[i] = fmaxf(fmaxf(s[i][0], s[i][1]), fmaxf(s[i][2], s[i][3]));
#pragma unroll
    for (int o = 8; o > 0; o >>= 1)
#pragma unroll
      for (int i = 0; i < 4; i++)
        mx[i] = fmaxf(mx[i], __shfl_xor_sync(0xffffffffu, mx[i], o));
    if (tx == 0) {
#pragma unroll
      for (int i = 0; i < 4; i++) {
        int r = ty * 4 + i;
        float mo = rowm[r];
        float mn = fmaxf(mo, mx[i]);
        rowm[r] = mn;
        rowa[r] = __expf(mo - mn);
      }
    }
    __syncthreads();

    float ls[4];
#pragma unroll
    for (int i = 0; i < 4; i++) {
      float mn = rowm[ty * 4 + i];
      ls[i] = 0.f;
#pragma unroll
      for (int j = 0; j < 4; j++) {
        float p = __expf(s[i][j] - mn);
        ps[(ty * 4 + i) * 65 + tx * 4 + j] = p;
        ls[i] += p;
      }
    }
#pragma unroll
    for (int o = 8; o > 0; o >>= 1)
#pragma unroll
      for (int i = 0; i < 4; i++)
        ls[i] += __shfl_xor_sync(0xffffffffu, ls[i], o);
    if (tx == 0)
#pragma unroll
      for (int i = 0; i < 4; i++) rowls[ty * 4 + i] = ls[i];
    __syncthreads();

    float al = rowa[rr];
#pragma unroll
    for (int c = 0; c < 18; c++) oacc[c] *= al;
#pragma unroll 2
    for (int kk = 0; kk < 64; kk++) {
      float p = ps[rr * 65 + kk];
      const float* vrow = vs + kk * 72 + cg * 18;
#pragma unroll
      for (int c = 0; c < 18; c++) oacc[c] = fmaf(p, vrow[c], oacc[c]);
    }
    if (cg == 0) rowl[rr] = rowl[rr] * al + rowls[rr];
    __syncthreads();
  }

  float inv = 1.f / rowl[rr];
  size_t off = obase + (size_t)(m0 + rr) * Hdim + cg * 18;
#pragma unroll
  for (int c = 0; c < 18; c++) {
    bf16 h, l;
    split_bf16(oacc[c] * inv, h, l);
    Ohi[off + c] = h;
    Olo[off + c] = l;
  }
}

// ------------------------------ launcher -----------------------------------
static float* sym_f(const void* s) { void* p; cudaGetSymbolAddress(&p, s); return (float*)p; }
static bf16*  sym_b(const void* s) { void* p; cudaGetSymbolAddress(&p, s); return (bf16*)p; }

extern "C" void kernel_launch(void* const* d_in, const int* in_sizes, int n_in,
                              void* d_out, int out_size) {
  (void)in_sizes; (void)n_in; (void)out_size;
  const float* x        = (const float*)d_in[0];
  const float* c        = (const float*)d_in[1];
  const float* t_emb    = (const float*)d_in[2];
  const float* qkv_w    = (const float*)d_in[3];
  const float* qkv_b    = (const float*)d_in[4];
  const float* proj_w   = (const float*)d_in[5];
  const float* proj_b   = (const float*)d_in[6];
  const float* to_q_w   = (const float*)d_in[7];
  const float* to_k_w   = (const float*)d_in[8];
  const float* to_v_w   = (const float*)d_in[9];
  const float* to_out_w = (const float*)d_in[10];
  const float* to_out_b = (const float*)d_in[11];
  const float* mlp_w1   = (const float*)d_in[12];
  const float* mlp_b1   = (const float*)d_in[13];
  const float* mlp_w2   = (const float*)d_in[14];
  const float* mlp_b2   = (const float*)d_in[15];
  const float* ada_w    = (const float*)d_in[16];
  const float* ada_b    = (const float*)d_in[17];
  float* out = (float*)d_out;

  float *mod = sym_f(&g_mod), *qkv = sym_f(&g_qkv), *xb = sym_f(&g_xb);
  float *kb = sym_f(&g_kb), *vb = sym_f(&g_vb);
  bf16 *lnh = sym_b(&g_ln_h), *lnl = sym_b(&g_ln_l);
  bf16 *ath = sym_b(&g_at_h), *atl = sym_b(&g_at_l);
  bf16 *xbh = sym_b(&g_xb_h), *xbl = sym_b(&g_xb_l);
  bf16 *hdh = sym_b(&g_hid_h), *hdl = sym_b(&g_hid_l);
  bf16 *ch = sym_b(&g_c_h), *cl = sym_b(&g_c_l);
  bf16 *wqkvh = sym_b(&g_wqkv_h), *wqkvl = sym_b(&g_wqkv_l);
  bf16 *wprh = sym_b(&g_wpr_h), *wprl = sym_b(&g_wpr_l);
  bf16 *wqh = sym_b(&g_wq_h), *wql = sym_b(&g_wq_l);
  bf16 *wkh = sym_b(&g_wk_h), *wkl = sym_b(&g_wk_l);
  bf16 *wvh = sym_b(&g_wv_h), *wvl = sym_b(&g_wv_l);
  bf16 *woh = sym_b(&g_wo_h), *wol = sym_b(&g_wo_l);
  bf16 *w1h = sym_b(&g_w1_h), *w1l = sym_b(&g_w1_l);
  bf16 *w2h = sym_b(&g_w2_h), *w2l = sym_b(&g_w2_l);

  cudaFuncSetAttribute(attn_kernel,
                       cudaFuncAttributeMaxDynamicSharedMemorySize, AT_SMEM);
#define SETSM(k) cudaFuncSetAttribute(k, \
    cudaFuncAttributeMaxDynamicSharedMemorySize, GSMEM)
  SETSM((gemm_tc<EPI_BIAS, true, false>));
  SETSM((gemm_tc<EPI_GELU, false, true>));
  SETSM((gemm_tc<EPI_RESGATE, true, true>));
  SETSM((gemm_tc<EPI_RESGATE, true, false>));
#undef SETSM

  float scale = 1.f / sqrtf((float)HeadD);

  // weight + context conversion to hi/lo planes
  auto cvt = [&](const float* src, bf16* h, bf16* l, int n) {
    cvt_kernel<<<(n / 4 + 255) / 256, 256>>>(src, h, l, n);
  };
  cvt(qkv_w,    wqkvh, wqkvl, 3 * Hdim * Hdim);
  cvt(proj_w,   wprh,  wprl,  Hdim * Hdim);
  cvt(to_q_w,   wqh,   wql,   Hdim * Hdim);
  cvt(to_k_w,   wkh,   wkl,   Hdim * CtxD);
  cvt(to_v_w,   wvh,   wvl,   Hdim * CtxD);
  cvt(to_out_w, woh,   wol,   Hdim * Hdim);
  cvt(mlp_w1,   w1h,   w1l,   MlpD * Hdim);
  cvt(mlp_w2,   w2h,   w2l,   Hdim * MlpD);
  cvt(c,        ch,    cl,    Crows * CtxD);

  // adaLN
  ada_kernel<<<ModW / 128, 128>>>(t_emb, ada_w, ada_b, mod);
  // LN + modulate (msa) -> bf16 planes
  ln_mod_kernel<<<Mrows, 256>>>(x, mod, 0, 1, lnh, lnl);
  // qkv
  {
    dim3 g(3 * Hdim / 128, Mrows / 128);
    gemm_tc<EPI_BIAS, true, false><<<g, 256, GSMEM>>>(
        lnh, lnl, wqkvh, wqkvl, qkv_b, nullptr, nullptr,
        qkv, nullptr, nullptr, Mrows, 3 * Hdim, Hdim);
  }
  // self-attention -> attno planes
  {
    dim3 g(Ntok / 64, NHead, Bsz);
    attn_kernel<<<g, 256, AT_SMEM>>>(
        qkv,            (long long)Ntok * 3 * Hdim, 3 * Hdim,
        qkv + Hdim,     (long long)Ntok * 3 * Hdim, 3 * Hdim,
        qkv + 2 * Hdim, (long long)Ntok * 3 * Hdim, 3 * Hdim,
        ath, atl, Ntok, scale);
  }
  // proj + gated residual -> xb (fp32 + planes)
  {
    dim3 g(Hdim / 128, Mrows / 128);
    gemm_tc<EPI_RESGATE, true, true><<<g, 256, GSMEM>>>(
        ath, atl, wprh, wprl, proj_b, x, mod + 2 * Hdim,
        xb, xbh, xbl, Mrows, Hdim, Hdim);
    // cross-attn Q (reuse qkv buffer as [Mrows, Hdim])
    gemm_tc<EPI_BIAS, true, false><<<g, 256, GSMEM>>>(
        xbh, xbl, wqh, wql, nullptr, nullptr, nullptr,
        qkv, nullptr, nullptr, Mrows, Hdim, Hdim);
  }
  // cross-attn K, V from context
  {
    dim3 g(Hdim / 128, (Crows + 127) / 128);
    gemm_tc<EPI_BIAS, true, false><<<g, 256, GSMEM>>>(
        ch, cl, wkh, wkl, nullptr, nullptr, nullptr,
        kb, nullptr, nullptr, Crows, Hdim, CtxD);
    gemm_tc<EPI_BIAS, true, false><<<g, 256, GSMEM>>>(
        ch, cl, wvh, wvl, nullptr, nullptr, nullptr,
        vb, nullptr, nullptr, Crows, Hdim, CtxD);
  }
  // cross-attention -> attno planes
  {
    dim3 g(Ntok / 64, NHead, Bsz);
    attn_kernel<<<g, 256, AT_SMEM>>>(
        qkv, (long long)Ntok * Hdim, Hdim,
        kb,  (long long)CtxT * Hdim, Hdim,
        vb,  (long long)CtxT * Hdim, Hdim,
        ath, atl, CtxT, scale);
  }
  // to_out + residual (in place on xb, fp32 only)
  {
    dim3 g(Hdim / 128, Mrows / 128);
    gemm_tc<EPI_RESGATE, true, false><<<g, 256, GSMEM>>>(
        ath, atl, woh, wol, to_out_b, xb, nullptr,
        xb, nullptr, nullptr, Mrows, Hdim, Hdim);
  }
  // LN + modulate (mlp)
  ln_mod_kernel<<<Mrows, 256>>>(xb, mod, 3, 4, lnh, lnl);
  // MLP
  {
    dim3 g1(MlpD / 128, Mrows / 128);
    gemm_tc<EPI_GELU, false, true><<<g1, 256, GSMEM>>>(
        lnh, lnl, w1h, w1l, mlp_b1, nullptr, nullptr,
        nullptr, hdh, hdl, Mrows, MlpD, Hdim);
    dim3 g2(Hdim / 128, Mrows / 128);
    gemm_tc<EPI_RESGATE, true, false><<<g2, 256, GSMEM>>>(
        hdh, hdl, w2h, w2l, mlp_b2, xb, mod + 5 * Hdim,
        out, nullptr, nullptr, Mrows, Hdim, MlpD);
  }
}

// round 4
// speedup vs baseline: 2.8366x; 1.4942x over previous
#include <cuda_runtime.h>
#include <cuda_bf16.h>
#include <math.h>
#include <stdint.h>

// ---------------------------------------------------------------------------
// DiT block. Round 4: bf16x3 tensor-core GEMMs + tensor-core flash attention.
// ---------------------------------------------------------------------------

#define Bsz   8
#define Ntok  1024
#define Hdim  1152
#define NHead 16
#define HeadD 72
#define CtxD  768
#define CtxT  77
#define MlpD  4608
#define Mrows (Bsz * Ntok)     // 8192
#define Crows (Bsz * CtxT)     // 616
#define ModW  (6 * Hdim)       // 6912

typedef __nv_bfloat16 bf16;
typedef __nv_bfloat162 bf162;

// ------------------------- scratch (no allocations) ------------------------
__device__ float g_mod [Bsz * ModW];
__device__ float g_xb  [Mrows * Hdim];

__device__ bf16 g_ln_h [Mrows * Hdim],  g_ln_l [Mrows * Hdim]; // ln out / xattn Q
__device__ bf16 g_at_h [Mrows * Hdim],  g_at_l [Mrows * Hdim]; // attn out
__device__ bf16 g_xb_h [Mrows * Hdim],  g_xb_l [Mrows * Hdim];
__device__ bf16 g_qkv_h[Mrows * 3 * Hdim], g_qkv_l[Mrows * 3 * Hdim];
__device__ bf16 g_kb_h [Crows * Hdim],  g_kb_l [Crows * Hdim];
__device__ bf16 g_vb_h [Crows * Hdim],  g_vb_l [Crows * Hdim];
__device__ bf16 g_hid_h[Mrows * MlpD],  g_hid_l[Mrows * MlpD];
__device__ bf16 g_c_h  [Crows * CtxD],  g_c_l  [Crows * CtxD];
__device__ bf16 g_wqkv_h[3 * Hdim * Hdim], g_wqkv_l[3 * Hdim * Hdim];
__device__ bf16 g_wpr_h [Hdim * Hdim],     g_wpr_l [Hdim * Hdim];
__device__ bf16 g_wq_h  [Hdim * Hdim],     g_wq_l  [Hdim * Hdim];
__device__ bf16 g_wk_h  [Hdim * CtxD],     g_wk_l  [Hdim * CtxD];
__device__ bf16 g_wv_h  [Hdim * CtxD],     g_wv_l  [Hdim * CtxD];
__device__ bf16 g_wo_h  [Hdim * Hdim],     g_wo_l  [Hdim * Hdim];
__device__ bf16 g_w1_h  [MlpD * Hdim],     g_w1_l  [MlpD * Hdim];
__device__ bf16 g_w2_h  [Hdim * MlpD],     g_w2_l  [Hdim * MlpD];

// ------------------------------ helpers ------------------------------------
__device__ __forceinline__ void split_bf16(float v, bf16& h, bf16& l) {
  h = __float2bfloat16(v);
  l = __float2bfloat16(v - __bfloat162float(h));
}
__device__ __forceinline__ float ex2(float x) {
  float y; asm("ex2.approx.f32 %0, %1;" : "=f"(y) : "f"(x)); return y;
}
__device__ __forceinline__ uint32_t prmt_hi(uint32_t a, uint32_t b) {
  uint32_t d; asm("prmt.b32 %0,%1,%2,0x7632;" : "=r"(d) : "r"(a), "r"(b));
  return d;
}
__device__ __forceinline__ uint32_t pack_bf2(float lo, float hi) {
  uint32_t d;
  asm("cvt.rn.bf16x2.f32 %0, %1, %2;" : "=r"(d) : "f"(hi), "f"(lo));
  return d;
}
__device__ __forceinline__ float truncf_bf(float x) {
  return __uint_as_float(__float_as_uint(x) & 0xFFFF0000u);
}

// -------------------- fused weight/context conversion ----------------------
struct CvtJobs {
  const float* src[9];
  bf16* hi[9];
  bf16* lo[9];
  int n[9];
};

__global__ __launch_bounds__(256) void cvt_all_kernel(CvtJobs J) {
  int t = blockIdx.y;
  int i = (blockIdx.x * 256 + threadIdx.x) * 4;
  if (i >= J.n[t]) return;
  float4 v = *(const float4*)(J.src[t] + i);
  bf16 h0, l0, h1, l1, h2, l2, h3, l3;
  split_bf16(v.x, h0, l0); split_bf16(v.y, h1, l1);
  split_bf16(v.z, h2, l2); split_bf16(v.w, h3, l3);
  bf16* hi = J.hi[t]; bf16* lo = J.lo[t];
  *(bf162*)(hi + i)     = __halves2bfloat162(h0, h1);
  *(bf162*)(hi + i + 2) = __halves2bfloat162(h2, h3);
  *(bf162*)(lo + i)     = __halves2bfloat162(l0, l1);
  *(bf162*)(lo + i + 2) = __halves2bfloat162(l2, l3);
}

// --------------------------- adaLN modulation ------------------------------
__global__ __launch_bounds__(128) void ada_kernel(
    const float* __restrict__ t_emb, const float* __restrict__ ada_w,
    const float* __restrict__ ada_b, float* __restrict__ mod) {
  __shared__ float se[Bsz * Hdim];
  int tid = threadIdx.x;
  for (int i = tid; i < Bsz * Hdim; i += 128) {
    float v = t_emb[i];
    se[i] = v / (1.f + __expf(-v));
  }
  __syncthreads();
  int j = blockIdx.x * 128 + tid;
  const float* w = ada_w + (size_t)j * Hdim;
  float acc[Bsz];
#pragma unroll
  for (int b = 0; b < Bsz; b++) acc[b] = 0.f;
  for (int k = 0; k < Hdim; k += 4) {
    float4 wv = *(const float4*)(w + k);
#pragma unroll
    for (int b = 0; b < Bsz; b++) {
      const float* s = se + b * Hdim + k;
      acc[b] += wv.x * s[0] + wv.y * s[1] + wv.z * s[2] + wv.w * s[3];
    }
  }
  float bb = ada_b[j];
#pragma unroll
  for (int b = 0; b < Bsz; b++) mod[b * ModW + j] = acc[b] + bb;
}

// ----------------- LayerNorm + modulate -> bf16 hi/lo -----------------------
__global__ __launch_bounds__(256) void ln_mod_kernel(
    const float* __restrict__ x, const float* __restrict__ mod,
    int sh_off, int sc_off, bf16* __restrict__ ohi, bf16* __restrict__ olo) {
  int row = blockIdx.x;
  int b = row >> 10;
  const float* xr = x + (size_t)row * Hdim;
  int tid = threadIdx.x;
  float s = 0.f, ss = 0.f;
  for (int i = tid; i < Hdim; i += 256) {
    float v = xr[i];
    s += v; ss += v * v;
  }
#pragma unroll
  for (int o = 16; o > 0; o >>= 1) {
    s  += __shfl_xor_sync(0xffffffffu, s, o);
    ss += __shfl_xor_sync(0xffffffffu, ss, o);
  }
  __shared__ float rs[8], rss[8], stat[2];
  int w = tid >> 5;
  if ((tid & 31) == 0) { rs[w] = s; rss[w] = ss; }
  __syncthreads();
  if (tid == 0) {
    float S = 0.f, SS = 0.f;
#pragma unroll
    for (int i = 0; i < 8; i++) { S += rs[i]; SS += rss[i]; }
    float mu = S * (1.f / Hdim);
    float var = SS * (1.f / Hdim) - mu * mu;
    stat[0] = mu;
    stat[1] = rsqrtf(var + 1e-6f);
  }
  __syncthreads();
  float mu = stat[0], rstd = stat[1];
  const float* sh = mod + b * ModW + sh_off * Hdim;
  const float* sc = mod + b * ModW + sc_off * Hdim;
  bf16* oh = ohi + (size_t)row * Hdim;
  bf16* ol = olo + (size_t)row * Hdim;
  for (int i = tid; i < Hdim; i += 256) {
    float v = (xr[i] - mu) * rstd * (1.f + sc[i]) + sh[i];
    bf16 h, l; split_bf16(v, h, l);
    oh[i] = h; ol[i] = l;
  }
}

// ------------------- tensor-core GEMM (NT, bf16 x3) -------------------------
__device__ __forceinline__ float gelu_tanh(float v) {
  const float c = 0.7978845608028654f;
  return 0.5f * v * (1.f + tanhf(c * (v + 0.044715f * v * v * v)));
}

#define EPI_BIAS    0
#define EPI_GELU    1
#define EPI_RESGATE 2

__device__ __forceinline__ void mma_bf16(float c[4], const uint32_t a[4],
                                         const uint32_t b[2]) {
  asm volatile(
      "mma.sync.aligned.m16n8k16.row.col.f32.bf16.bf16.f32 "
      "{%0,%1,%2,%3}, {%4,%5,%6,%7}, {%8,%9}, {%0,%1,%2,%3};"
      : "+f"(c[0]), "+f"(c[1]), "+f"(c[2]), "+f"(c[3])
      : "r"(a[0]), "r"(a[1]), "r"(a[2]), "r"(a[3]), "r"(b[0]), "r"(b[1]));
}

__device__ __forceinline__ void ldsm4(uint32_t r[4], uint32_t addr) {
  asm volatile("ldmatrix.sync.aligned.m8n8.x4.shared.b16 {%0,%1,%2,%3}, [%4];"
               : "=r"(r[0]), "=r"(r[1]), "=r"(r[2]), "=r"(r[3]) : "r"(addr));
}
__device__ __forceinline__ void ldsm4t(uint32_t r[4], uint32_t addr) {
  asm volatile(
      "ldmatrix.sync.aligned.m8n8.x4.trans.shared.b16 {%0,%1,%2,%3}, [%4];"
      : "=r"(r[0]), "=r"(r[1]), "=r"(r[2]), "=r"(r[3]) : "r"(addr));
}

__device__ __forceinline__ void cp16(uint32_t dst, const void* src, bool p) {
  int sz = p ? 16 : 0;
  asm volatile("cp.async.cg.shared.global [%0], [%1], 16, %2;\n"
               :: "r"(dst), "l"(src), "r"(sz));
}

#define TILE_B  10240
#define STAGE_B 40960
#define GSMEM   (2 * STAGE_B)

template <int EPI, bool OUTF, bool OUTB>
__global__ __launch_bounds__(256, 2) void gemm_tc(
    const bf16* __restrict__ Ah, const bf16* __restrict__ Al,
    const bf16* __restrict__ Wh, const bf16* __restrict__ Wl,
    const float* __restrict__ bias, const float* __restrict__ res,
    const float* __restrict__ gate, float* __restrict__ C,
    bf16* __restrict__ Chi, bf16* __restrict__ Clo,
    int M, int N, int K) {
  extern __shared__ char smc[];
  uint32_t sbase = (uint32_t)__cvta_generic_to_shared(smc);
  int tid = threadIdx.x;
  int warp = tid >> 5, lane = tid & 31;
  int wm = warp & 3, wn = warp >> 2;
  int m0 = blockIdx.y << 7, n0 = blockIdx.x << 7;

  float acc[2][8][4];
#pragma unroll
  for (int mt = 0; mt < 2; mt++)
#pragma unroll
    for (int nt = 0; nt < 8; nt++)
#pragma unroll
      for (int f = 0; f < 4; f++) acc[mt][nt][f] = 0.f;

  int lq = lane & 7, lb = (lane >> 3) & 1, lh = lane >> 4;
  uint32_t offA[2], offB[4];
#pragma unroll
  for (int mt = 0; mt < 2; mt++)
    offA[mt] = (uint32_t)((wm * 32 + mt * 16 + lq + lb * 8) * 80 + lh * 16);
#pragma unroll
  for (int j = 0; j < 4; j++)
    offB[j] = (uint32_t)(2 * TILE_B +
                         (wn * 64 + j * 16 + lq + lh * 8) * 80 + lb * 16);

  int r0c = tid >> 2, c0b = (tid & 3) * 16;
  int r1c = (tid + 256) >> 2, c1b = ((tid + 256) & 3) * 16;

  const int nk = K >> 5;

  auto issue = [&](int k0, int s) {
    uint32_t st = sbase + s * STAGE_B;
#pragma unroll
    for (int i = 0; i < 2; i++) {
      int row = i ? r1c : r0c;
      int cb  = i ? c1b : c0b;
      int ce  = cb >> 1;
      bool am = (m0 + row) < M;
      int ra = am ? (m0 + row) : 0;
      uint32_t d = st + row * 80 + cb;
      cp16(d,              Ah + (size_t)ra * K + k0 + ce, am);
      cp16(d + TILE_B,     Al + (size_t)ra * K + k0 + ce, am);
      cp16(d + 2 * TILE_B, Wh + (size_t)(n0 + row) * K + k0 + ce, true);
      cp16(d + 3 * TILE_B, Wl + (size_t)(n0 + row) * K + k0 + ce, true);
    }
    asm volatile("cp.async.commit_group;\n");
  };

  issue(0, 0);
  for (int kt = 0; kt < nk; kt++) {
    int s = kt & 1;
    if (kt + 1 < nk) {
      issue((kt + 1) << 5, s ^ 1);
      asm volatile("cp.async.wait_group 1;\n");
    } else {
      asm volatile("cp.async.wait_group 0;\n");
    }
    __syncthreads();

    uint32_t sb = sbase + s * STAGE_B;
#pragma unroll
    for (int ks = 0; ks < 2; ks++) {
      uint32_t ah[2][4], al[2][4];
#pragma unroll
      for (int mt = 0; mt < 2; mt++) {
        ldsm4(ah[mt], sb + offA[mt] + ks * 32);
        ldsm4(al[mt], sb + offA[mt] + TILE_B + ks * 32);
      }
#pragma unroll
      for (int j = 0; j < 4; j++) {
        uint32_t bh[4], bl[4];
        ldsm4(bh, sb + offB[j] + ks * 32);
        ldsm4(bl, sb + offB[j] + TILE_B + ks * 32);
#pragma unroll
        for (int mt = 0; mt < 2; mt++) {
          mma_bf16(acc[mt][2 * j],     ah[mt], bh);
          mma_bf16(acc[mt][2 * j],     ah[mt], bl);
          mma_bf16(acc[mt][2 * j],     al[mt], bh);
          mma_bf16(acc[mt][2 * j + 1], ah[mt], bh + 2);
          mma_bf16(acc[mt][2 * j + 1], ah[mt], bl + 2);
          mma_bf16(acc[mt][2 * j + 1], al[mt], bh + 2);
        }
      }
    }
    __syncthreads();
  }

  int g = lane >> 2, tg = lane & 3;
#pragma unroll
  for (int mt = 0; mt < 2; mt++) {
#pragma unroll
    for (int half = 0; half < 2; half++) {
      int m = m0 + wm * 32 + mt * 16 + g + half * 8;
      if (m >= M) continue;
      int bq = m >> 10;
#pragma unroll
      for (int nt = 0; nt < 8; nt++) {
        int n = n0 + wn * 64 + nt * 8 + tg * 2;
        float v0 = acc[mt][nt][half * 2 + 0];
        float v1 = acc[mt][nt][half * 2 + 1];
        if (bias) { v0 += bias[n]; v1 += bias[n + 1]; }
        if (EPI == EPI_GELU) { v0 = gelu_tanh(v0); v1 = gelu_tanh(v1); }
        if (EPI == EPI_RESGATE) {
          float g0 = 1.f, g1 = 1.f;
          if (gate) { g0 = gate[bq * ModW + n]; g1 = gate[bq * ModW + n + 1]; }
          v0 = res[(size_t)m * N + n] + g0 * v0;
          v1 = res[(size_t)m * N + n + 1] + g1 * v1;
        }
        if (OUTF)
          *(float2*)(C + (size_t)m * N + n) = make_float2(v0, v1);
        if (OUTB) {
          bf16 h0, l0, h1, l1;
          split_bf16(v0, h0, l0);
          split_bf16(v1, h1, l1);
          *(bf162*)(Chi + (size_t)m * N + n) = __halves2bfloat162(h0, h1);
          *(bf162*)(Clo + (size_t)m * N + n) = __halves2bfloat162(l0, l1);
        }
      }
    }
  }
}

// ---------------- tensor-core flash attention (bf16 x3) ---------------------
// 128 q-rows x 128 kv per iter, 8 warps, warp owns 16 q-rows.
// smem: Qh,Ql + double-buffered (Kh,Kl,Vh,Vl); row stride 88 bf16 = 176 B.
#define AHP   88
#define ARB   176
#define APL   (128 * ARB)          // 22528 B per plane
#define AKVST (4 * APL)            // 90112 B per KV stage
#define ATSM  (2 * APL + 2 * AKVST)  // 225280 B

__global__ __launch_bounds__(256) void attn_tc(
    const bf16* __restrict__ Qh, const bf16* __restrict__ Ql,
    long long qbs, int ldq,
    const bf16* __restrict__ Kh, const bf16* __restrict__ Kl,
    const bf16* __restrict__ Vh, const bf16* __restrict__ Vl,
    long long kbs, int ldk,
    bf16* __restrict__ Oh, bf16* __restrict__ Ol,
    int kv_len, float sl2e) {
  extern __shared__ char smb[];
  uint32_t sb = (uint32_t)__cvta_generic_to_shared(smb);
  int b = blockIdx.z, h = blockIdx.y;
  int m0 = blockIdx.x * 128;
  int tid = threadIdx.x, warp = tid >> 5, lane = tid & 31;
  int g = lane >> 2, tg = lane & 3;
  int lq = lane & 7, lb = (lane >> 3) & 1, lh = lane >> 4;

  const bf16* Qhb = Qh + (size_t)b * qbs + (size_t)m0 * ldq + h * HeadD;
  const bf16* Qlb = Ql + (size_t)b * qbs + (size_t)m0 * ldq + h * HeadD;
  const bf16* Khb = Kh + (size_t)b * kbs + h * HeadD;
  const bf16* Klb = Kl + (size_t)b * kbs + h * HeadD;
  const bf16* Vhb = Vh + (size_t)b * kbs + h * HeadD;
  const bf16* Vlb = Vl + (size_t)b * kbs + h * HeadD;

  // zero hd-padding (cols 72..87) of all 10 planes
  for (int i = tid; i < 1280; i += 256) {
    int p = i >> 7, r = i & 127;
    uint32_t ad = sb + p * APL + r * ARB + 144;
    asm volatile("st.shared.v4.b32 [%0], {%1,%1,%1,%1};" :: "r"(ad), "r"(0));
    asm volatile("st.shared.v4.b32 [%0], {%1,%1,%1,%1};"
                 :: "r"(ad + 16), "r"(0));
  }

  // load Q (128 rows x 9 16B-chunks x 2 planes)
  for (int i = tid; i < 1152; i += 256) {
    int r = i / 9, ch = i % 9;
    uint32_t d = sb + r * ARB + ch * 16;
    cp16(d,       Qhb + (size_t)r * ldq + ch * 8, true);
    cp16(d + APL, Qlb + (size_t)r * ldq + ch * 8, true);
  }

  auto loadKV = [&](int j0, int s) {
    uint32_t st = sb + 2 * APL + s * AKVST;
    for (int i = tid; i < 1152; i += 256) {
      int r = i / 9, ch = i % 9;
      bool ok = (j0 + r) < kv_len;
      int rc = ok ? (j0 + r) : 0;
      size_t off = (size_t)rc * ldk + ch * 8;
      uint32_t d = st + r * ARB + ch * 16;
      cp16(d,           Khb + off, ok);
      cp16(d + APL,     Klb + off, ok);
      cp16(d + 2 * APL, Vhb + off, ok);
      cp16(d + 3 * APL, Vlb + off, ok);
    }
    asm volatile("cp.async.commit_group;\n");
  };

  int iters = (kv_len + 127) >> 7;
  loadKV(0, 0);                      // group 0 (includes Q chunks)
  if (iters > 1) loadKV(128, 1);     // group 1

  float m0r = -1e30f, m1r = -1e30f, ls0 = 0.f, ls1 = 0.f;
  float oacc[9][4];
#pragma unroll
  for (int nt = 0; nt < 9; nt++)
#pragma unroll
    for (int f = 0; f < 4; f++) oacc[nt][f] = 0.f;

  uint32_t offA = (uint32_t)((warp * 16 + lq + lb * 8) * ARB + lh * 16);
  uint32_t offB = (uint32_t)((lq + lh * 8) * ARB + lb * 16);
  uint32_t offV = (uint32_t)((lq + lb * 8) * ARB + lh * 16);

  for (int it = 0; it < iters; it++) {
    if (it + 1 < iters) {
      if (it > 0) loadKV((it + 1) * 128, (it + 1) & 1);
      asm volatile("cp.async.wait_group 1;\n");
    } else {
      asm volatile("cp.async.wait_group 0;\n");
    }
    __syncthreads();

    uint32_t kbse = sb + 2 * APL + (it & 1) * AKVST;

    // ---- S = Q K^T (3-term) ----
    float sa[16][4];
#pragma unroll
    for (int j = 0; j < 16; j++)
#pragma unroll
      for (int f = 0; f < 4; f++) sa[j][f] = 0.f;

#pragma unroll
    for (int ks = 0; ks < 5; ks++) {
      uint32_t ah[4], al_[4];
      ldsm4(ah,  sb + offA + ks * 32);
      ldsm4(al_, sb + APL + offA + ks * 32);
#pragma unroll
      for (int nt = 0; nt < 8; nt++) {
        uint32_t bh[4], bl[4];
        ldsm4(bh, kbse + offB + nt * 16 * ARB + ks * 32);
        ldsm4(bl, kbse + APL + offB + nt * 16 * ARB + ks * 32);
        mma_bf16(sa[2 * nt],     ah,  bh);
        mma_bf16(sa[2 * nt],     ah,  bl);
        mma_bf16(sa[2 * nt],     al_, bh);
        mma_bf16(sa[2 * nt + 1], ah,  bh + 2);
        mma_bf16(sa[2 * nt + 1], ah,  bl + 2);
        mma_bf16(sa[2 * nt + 1], al_, bh + 2);
      }
    }

    // ---- online softmax (warp-local rows) ----
    int j0 = it * 128;
    bool msk = (j0 + 128) > kv_len;
    float mx0 = -1e30f, mx1 = -1e30f;
#pragma unroll
    for (int j = 0; j < 16; j++) {
#pragma unroll
      for (int e = 0; e < 4; e++) {
        float v = sa[j][e] * sl2e;
        if (msk) {
          int col = j * 8 + 2 * tg + (e & 1);
          if (j0 + col >= kv_len) v = -1e30f;
        }
        sa[j][e] = v;
      }
      mx0 = fmaxf(mx0, fmaxf(sa[j][0], sa[j][1]));
      mx1 = fmaxf(mx1, fmaxf(sa[j][2], sa[j][3]));
    }
    mx0 = fmaxf(mx0, __shfl_xor_sync(0xffffffffu, mx0, 1));
    mx0 = fmaxf(mx0, __shfl_xor_sync(0xffffffffu, mx0, 2));
    mx1 = fmaxf(mx1, __shfl_xor_sync(0xffffffffu, mx1, 1));
    mx1 = fmaxf(mx1, __shfl_xor_sync(0xffffffffu, mx1, 2));
    float mn0 = fmaxf(m0r, mx0), mn1 = fmaxf(m1r, mx1);
    float al0 = ex2(m0r - mn0), al1 = ex2(m1r - mn1);
    m0r = mn0; m1r = mn1;

    float s0 = 0.f, s1 = 0.f;
#pragma unroll
    for (int j = 0; j < 16; j++) {
      float p0 = ex2(sa[j][0] - mn0), p1 = ex2(sa[j][1] - mn0);
      float p2 = ex2(sa[j][2] - mn1), p3 = ex2(sa[j][3] - mn1);
      sa[j][0] = p0; sa[j][1] = p1; sa[j][2] = p2; sa[j][3] = p3;
      s0 += p0 + p1; s1 += p2 + p3;
    }
    s0 += __shfl_xor_sync(0xffffffffu, s0, 1);
    s0 += __shfl_xor_sync(0xffffffffu, s0, 2);
    s1 += __shfl_xor_sync(0xffffffffu, s1, 1);
    s1 += __shfl_xor_sync(0xffffffffu, s1, 2);
    ls0 = ls0 * al0 + s0;
    ls1 = ls1 * al1 + s1;
#pragma unroll
    for (int nt = 0; nt < 9; nt++) {
      oacc[nt][0] *= al0; oacc[nt][1] *= al0;
      oacc[nt][2] *= al1; oacc[nt][3] *= al1;
    }

    // ---- O += P V (3-term, P split hi/lo on the fly) ----
    uint32_t vbse = kbse + 2 * APL;
#pragma unroll
    for (int kc = 0; kc < 8; kc++) {
      uint32_t pah[4], pal[4];
#pragma unroll
      for (int jj = 0; jj < 2; jj++) {
        int j = 2 * kc + jj;
        uint32_t u0 = __float_as_uint(sa[j][0]);
        uint32_t u1 = __float_as_uint(sa[j][1]);
        uint32_t u2 = __float_as_uint(sa[j][2]);
        uint32_t u3 = __float_as_uint(sa[j][3]);
        pah[2 * jj]     = prmt_hi(u0, u1);
        pah[2 * jj + 1] = prmt_hi(u2, u3);
        pal[2 * jj]     = pack_bf2(sa[j][0] - truncf_bf(sa[j][0]),
                                   sa[j][1] - truncf_bf(sa[j][1]));
        pal[2 * jj + 1] = pack_bf2(sa[j][2] - truncf_bf(sa[j][2]),
                                   sa[j][3] - truncf_bf(sa[j][3]));
      }
      // reorder to A-frag {a0,a1,a2,a3} = {j0 rowg, j0 rowg8, j1 rowg, j1 rowg8}
      // pah already in that order: [0]=j0 rows g; [1]=j0 rows g+8; [2],[3]=j1.
#pragma unroll
      for (int np = 0; np < 5; np++) {
        uint32_t vh[4], vl[4];
        ldsm4t(vh, vbse + offV + kc * 16 * ARB + np * 32);
        ldsm4t(vl, vbse + APL + offV + kc * 16 * ARB + np * 32);
        mma_bf16(oacc[2 * np], pah, vh);
        mma_bf16(oacc[2 * np], pah, vl);
        mma_bf16(oacc[2 * np], pal, vh);
        if (np < 4) {
          mma_bf16(oacc[2 * np + 1], pah, vh + 2);
          mma_bf16(oacc[2 * np + 1], pah, vl + 2);
          mma_bf16(oacc[2 * np + 1], pal, vh + 2);
        }
      }
    }
    __syncthreads();
  }

  // ---- write O planes ----
  float inv0 = 1.f / ls0, inv1 = 1.f / ls1;
  int r0 = m0 + warp * 16 + g, r1 = r0 + 8;
  size_t base0 = ((size_t)b * Ntok + r0) * Hdim + h * HeadD;
  size_t base1 = ((size_t)b * Ntok + r1) * Hdim + h * HeadD;
#pragma unroll
  for (int nt = 0; nt < 9; nt++) {
    int col = nt * 8 + 2 * tg;
    float v0 = oacc[nt][0] * inv0, v1 = oacc[nt][1] * inv0;
    float v2 = oacc[nt][2] * inv1, v3 = oacc[nt][3] * inv1;
    bf16 h0, l0, h1, l1, h2, l2, h3, l3;
    split_bf16(v0, h0, l0); split_bf16(v1, h1, l1);
    split_bf16(v2, h2, l2); split_bf16(v3, h3, l3);
    *(bf162*)(Oh + base0 + col) = __halves2bfloat162(h0, h1);
    *(bf162*)(Ol + base0 + col) = __halves2bfloat162(l0, l1);
    *(bf162*)(Oh + base1 + col) = __halves2bfloat162(h2, h3);
    *(bf162*)(Ol + base1 + col) = __halves2bfloat162(l2, l3);
  }
}

// ------------------------------ launcher -----------------------------------
static float* sym_f(const void* s) { void* p; cudaGetSymbolAddress(&p, s); return (float*)p; }
static bf16*  sym_b(const void* s) { void* p; cudaGetSymbolAddress(&p, s); return (bf16*)p; }

extern "C" void kernel_launch(void* const* d_in, const int* in_sizes, int n_in,
                              void* d_out, int out_size) {
  (void)in_sizes; (void)n_in; (void)out_size;
  const float* x        = (const float*)d_in[0];
  const float* c        = (const float*)d_in[1];
  const float* t_emb    = (const float*)d_in[2];
  const float* qkv_w    = (const float*)d_in[3];
  const float* qkv_b    = (const float*)d_in[4];
  const float* proj_w   = (const float*)d_in[5];
  const float* proj_b   = (const float*)d_in[6];
  const float* to_q_w   = (const float*)d_in[7];
  const float* to_k_w   = (const float*)d_in[8];
  const float* to_v_w   = (const float*)d_in[9];
  const float* to_out_w = (const float*)d_in[10];
  const float* to_out_b = (const float*)d_in[11];
  const float* mlp_w1   = (const float*)d_in[12];
  const float* mlp_b1   = (const float*)d_in[13];
  const float* mlp_w2   = (const float*)d_in[14];
  const float* mlp_b2   = (const float*)d_in[15];
  const float* ada_w    = (const float*)d_in[16];
  const float* ada_b    = (const float*)d_in[17];
  float* out = (float*)d_out;

  float *mod = sym_f(&g_mod), *xb = sym_f(&g_xb);
  bf16 *lnh = sym_b(&g_ln_h), *lnl = sym_b(&g_ln_l);
  bf16 *ath = sym_b(&g_at_h), *atl = sym_b(&g_at_l);
  bf16 *xbh = sym_b(&g_xb_h), *xbl = sym_b(&g_xb_l);
  bf16 *qkh = sym_b(&g_qkv_h), *qkl = sym_b(&g_qkv_l);
  bf16 *kbh = sym_b(&g_kb_h), *kbl = sym_b(&g_kb_l);
  bf16 *vbh = sym_b(&g_vb_h), *vbl = sym_b(&g_vb_l);
  bf16 *hdh = sym_b(&g_hid_h), *hdl = sym_b(&g_hid_l);
  bf16 *ch = sym_b(&g_c_h), *cl = sym_b(&g_c_l);
  bf16 *wqkvh = sym_b(&g_wqkv_h), *wqkvl = sym_b(&g_wqkv_l);
  bf16 *wprh = sym_b(&g_wpr_h), *wprl = sym_b(&g_wpr_l);
  bf16 *wqh = sym_b(&g_wq_h), *wql = sym_b(&g_wq_l);
  bf16 *wkh = sym_b(&g_wk_h), *wkl = sym_b(&g_wk_l);
  bf16 *wvh = sym_b(&g_wv_h), *wvl = sym_b(&g_wv_l);
  bf16 *woh = sym_b(&g_wo_h), *wol = sym_b(&g_wo_l);
  bf16 *w1h = sym_b(&g_w1_h), *w1l = sym_b(&g_w1_l);
  bf16 *w2h = sym_b(&g_w2_h), *w2l = sym_b(&g_w2_l);

  cudaFuncSetAttribute(attn_tc,
                       cudaFuncAttributeMaxDynamicSharedMemorySize, ATSM);
#define SETSM(k) cudaFuncSetAttribute(k, \
    cudaFuncAttributeMaxDynamicSharedMemorySize, GSMEM)
  SETSM((gemm_tc<EPI_BIAS, false, true>));
  SETSM((gemm_tc<EPI_GELU, false, true>));
  SETSM((gemm_tc<EPI_RESGATE, true, true>));
  SETSM((gemm_tc<EPI_RESGATE, true, false>));
#undef SETSM

  const float sl2e = (1.f / sqrtf((float)HeadD)) * 1.4426950408889634f;

  // 0: fused conversions
  {
    CvtJobs J;
    const float* s[9] = {qkv_w, proj_w, to_q_w, to_k_w, to_v_w,
                         to_out_w, mlp_w1, mlp_w2, c};
    bf16* hh[9] = {wqkvh, wprh, wqh, wkh, wvh, woh, w1h, w2h, ch};
    bf16* ll[9] = {wqkvl, wprl, wql, wkl, wvl, wol, w1l, w2l, cl};
    int nn[9] = {3 * Hdim * Hdim, Hdim * Hdim, Hdim * Hdim, Hdim * CtxD,
                 Hdim * CtxD, Hdim * Hdim, MlpD * Hdim, Hdim * MlpD,
                 Crows * CtxD};
    for (int i = 0; i < 9; i++) { J.src[i] = s[i]; J.hi[i] = hh[i];
                                  J.lo[i] = ll[i]; J.n[i] = nn[i]; }
    dim3 g((MlpD * Hdim / 4 + 255) / 256, 9);
    cvt_all_kernel<<<g, 256>>>(J);
  }
  // 1: adaLN
  ada_kernel<<<ModW / 128, 128>>>(t_emb, ada_w, ada_b, mod);
  // 2: LN + modulate (msa)
  ln_mod_kernel<<<Mrows, 256>>>(x, mod, 0, 1, lnh, lnl);
  // 3: qkv GEMM -> bf16 planes
  {
    dim3 g(3 * Hdim / 128, Mrows / 128);
    gemm_tc<EPI_BIAS, false, true><<<g, 256, GSMEM>>>(
        lnh, lnl, wqkvh, wqkvl, qkv_b, nullptr, nullptr,
        nullptr, qkh, qkl, Mrows, 3 * Hdim, Hdim);
  }
  // 4: self-attention
  {
    dim3 g(Ntok / 128, NHead, Bsz);
    attn_tc<<<g, 256, ATSM>>>(
        qkh, qkl, (long long)Ntok * 3 * Hdim, 3 * Hdim,
        qkh + Hdim, qkl + Hdim, qkh + 2 * Hdim, qkl + 2 * Hdim,
        (long long)Ntok * 3 * Hdim, 3 * Hdim,
        ath, atl, Ntok, sl2e);
  }
  // 5: proj + gated residual -> xb fp32 + planes
  {
    dim3 g(Hdim / 128, Mrows / 128);
    gemm_tc<EPI_RESGATE, true, true><<<g, 256, GSMEM>>>(
        ath, atl, wprh, wprl, proj_b, x, mod + 2 * Hdim,
        xb, xbh, xbl, Mrows, Hdim, Hdim);
    // 6: cross-attn Q -> ln planes (reuse)
    gemm_tc<EPI_BIAS, false, true><<<g, 256, GSMEM>>>(
        xbh, xbl, wqh, wql, nullptr, nullptr, nullptr,
        nullptr, lnh, lnl, Mrows, Hdim, Hdim);
  }
  // 7,8: cross-attn K, V
  {
    dim3 g(Hdim / 128, (Crows + 127) / 128);
    gemm_tc<EPI_BIAS, false, true><<<g, 256, GSMEM>>>(
        ch, cl, wkh, wkl, nullptr, nullptr, nullptr,
        nullptr, kbh, kbl, Crows, Hdim, CtxD);
    gemm_tc<EPI_BIAS, false, true><<<g, 256, GSMEM>>>(
        ch, cl, wvh, wvl, nullptr, nullptr, nullptr,
        nullptr, vbh, vbl, Crows, Hdim, CtxD);
  }
  // 9: cross-attention
  {
    dim3 g(Ntok / 128, NHead, Bsz);
    attn_tc<<<g, 256, ATSM>>>(
        lnh, lnl, (long long)Ntok * Hdim, Hdim,
        kbh, kbl, vbh, vbl, (long long)CtxT * Hdim, Hdim,
        ath, atl, CtxT, sl2e);
  }
  // 10: to_out + residual -> xb
  {
    dim3 g(Hdim / 128, Mrows / 128);
    gemm_tc<EPI_RESGATE, true, false><<<g, 256, GSMEM>>>(
        ath, atl, woh, wol, to_out_b, xb, nullptr,
        xb, nullptr, nullptr, Mrows, Hdim, Hdim);
  }
  // 11: LN + modulate (mlp)
  ln_mod_kernel<<<Mrows, 256>>>(xb, mod, 3, 4, lnh, lnl);
  // 12, 13: MLP
  {
    dim3 g1(MlpD / 128, Mrows / 128);
    gemm_tc<EPI_GELU, false, true><<<g1, 256, GSMEM>>>(
        lnh, lnl, w1h, w1l, mlp_b1, nullptr, nullptr,
        nullptr, hdh, hdl, Mrows, MlpD, Hdim);
    dim3 g2(Hdim / 128, Mrows / 128);
    gemm_tc<EPI_RESGATE, true, false><<<g2, 256, GSMEM>>>(
        hdh, hdl, w2h, w2l, mlp_b2, xb, mod + 5 * Hdim,
        out, nullptr, nullptr, Mrows, Hdim, MlpD);
  }
}